// round 15
// baseline (speedup 1.0000x reference)
#include <cuda_runtime.h>
#include <cuda_fp16.h>
#include <cstdint>

// CliffordLinear == dense GEMM: out[b,n] = sum_k X[b,k]*Weff[n,k] + bias[n]
//   Weff[o*8+l, i*8+kb] = cayley[kb^l, kb, l] * W[o, i, kb^l]
// Single-pass fp16 HMMA (fp32 accumulate), with A(x) fp32->fp16 conversion
// FUSED into the GEMM (register-pipelined LDG+CVT+STS), B precomputed.

#define NB     8
#define CIN    256
#define BATCH  8192
#define KDIM   2048
#define NDIM   2048

#define BM 128
#define BN 128
#define BK 32
#define KT (KDIM / BK)          // 64 k-tiles
#define STAGES 3

#define ROWB 80                 // 64B data + 16B pad per smem row
#define TENSOR_BYTES (128 * ROWB)               // 10240
#define STAGE_BYTES  (2 * TENSOR_BYTES)         // 20480 (A + B)
#define SMEM_TOTAL   (STAGES * STAGE_BYTES)     // 61440

// ---- scratch (static device array; no allocs) ----
__device__ __half g_Bh[(size_t)NDIM * KDIM];

__global__ void build_weff_kernel(const float* __restrict__ W,
                                  const float* __restrict__ C) {
    int idx = blockIdx.x * blockDim.x + threadIdx.x;  // n*KDIM + k
    int k = idx & (KDIM - 1);
    int n = idx >> 11;
    int kb = k & 7, i = k >> 3;
    int l = n & 7, o = n >> 3;
    int j = kb ^ l;
    float w = C[(j * 8 + kb) * 8 + l] * W[(o * CIN + i) * NB + j];
    g_Bh[idx] = __float2half_rn(w);
}

// ---- mma / cp.async helpers (sm80-level PTX only; compute_103-safe) ----
__device__ __forceinline__ void mma_f16(float* c, const uint32_t* a, const uint32_t* b) {
    asm volatile(
        "mma.sync.aligned.m16n8k16.row.col.f32.f16.f16.f32 "
        "{%0,%1,%2,%3}, {%4,%5,%6,%7}, {%8,%9}, {%0,%1,%2,%3};"
        : "+f"(c[0]), "+f"(c[1]), "+f"(c[2]), "+f"(c[3])
        : "r"(a[0]), "r"(a[1]), "r"(a[2]), "r"(a[3]), "r"(b[0]), "r"(b[1]));
}
__device__ __forceinline__ void cpa16(void* dst, const void* src) {
    uint32_t d = (uint32_t)__cvta_generic_to_shared(dst);
    asm volatile("cp.async.cg.shared.global [%0], [%1], 16;" :: "r"(d), "l"(src));
}
__device__ __forceinline__ uint32_t cvt2(float lo, float hi) {
    uint32_t r;
    asm("cvt.rn.f16x2.f32 %0, %1, %2;" : "=r"(r) : "f"(hi), "f"(lo));
    return r;
}

__global__ __launch_bounds__(256, 2)
void clifford_hmma_kernel(const float* __restrict__ x,
                          const float* __restrict__ bias,
                          float* __restrict__ out) {
    extern __shared__ char smem[];

    const int tid = threadIdx.x;
    const int lane = tid & 31;
    const int wid = tid >> 5;           // 0..7
    const int wr = wid >> 2;            // 0..1
    const int wc = wid & 3;             // 0..3
    const int g   = lane >> 2;          // 0..7
    const int tg2 = (lane & 3) * 2;     // 0,2,4,6
    const int bx = blockIdx.x, by = blockIdx.y;

    const size_t rowA0 = (size_t)bx * BM;
    const size_t rowB0 = (size_t)by * BN;

    // B cp.async mapping: 2 chunks of 16B per thread per stage
    const int c0 = tid * 2;
    auto load_B = [&](int kt, int slot) {
        const int k0 = kt * BK;
        char* stB = smem + slot * STAGE_BYTES + TENSOR_BYTES;
#pragma unroll
        for (int q = 0; q < 2; q++) {
            int c = c0 + q;
            int r = c >> 2, cb = (c & 3);
            cpa16(stB + r * ROWB + cb * 16,
                  g_Bh + (rowB0 + r) * KDIM + k0 + cb * 8);
        }
        asm volatile("cp.async.commit_group;" ::: "memory");
    };

    // A fp32 path: each thread owns half a row: row ar = tid>>1, 16 floats
    // (64 bytes) at float col ac = (tid&1)*16.
    const int ar = tid >> 1;
    const int ac = (tid & 1) * 16;
    const float* xrow = x + (rowA0 + ar) * KDIM + ac;
    float4 aregs[4];                    // prefetched stage (fp32)
    auto ldg_A = [&](int kt) {
        const float4* p = (const float4*)(xrow + kt * BK);
        aregs[0] = p[0]; aregs[1] = p[1]; aregs[2] = p[2]; aregs[3] = p[3];
    };
    auto sts_A = [&](int slot) {
        char* dst = smem + slot * STAGE_BYTES + ar * ROWB + ac * 2;
#pragma unroll
        for (int q = 0; q < 4; q++) {
            uint32_t h0 = cvt2(aregs[q].x, aregs[q].y);
            uint32_t h1 = cvt2(aregs[q].z, aregs[q].w);
            uint2 v = {h0, h1};
            *(uint2*)(dst + q * 8) = v;
        }
    };

    float acc[4][4][4];
#pragma unroll
    for (int mi = 0; mi < 4; mi++)
#pragma unroll
        for (int ni = 0; ni < 4; ni++)
#pragma unroll
            for (int r = 0; r < 4; r++) acc[mi][ni][r] = 0.0f;

    // prologue: A stages 0,1 into smem, stage 2 in regs; B stages 0,1 in flight
    ldg_A(0); sts_A(0);
    ldg_A(1); sts_A(1);
    ldg_A(2);
    load_B(0, 0);
    load_B(1, 1);

    for (int it = 0; it < KT; it++) {
        if (it < KT - 1) asm volatile("cp.async.wait_group 1;" ::: "memory");
        else             asm volatile("cp.async.wait_group 0;" ::: "memory");
        __syncthreads();
        if (it + 2 < KT) {
            load_B(it + 2, (it + 2) % STAGES);
            sts_A((it + 2) % STAGES);     // regs hold stage it+2
        }
        if (it + 3 < KT) ldg_A(it + 3);   // overwrite regs; latency hidden

        const char* st = smem + (it % STAGES) * STAGE_BYTES;
        const char* sA = st;
        const char* sB = st + TENSOR_BYTES;

#pragma unroll
        for (int kk = 0; kk < BK; kk += 16) {
            uint32_t a[4][4], b[4][2];
#pragma unroll
            for (int mi = 0; mi < 4; mi++) {
                int r0 = wr * 64 + mi * 16 + g;
                const char* p0 = sA + r0 * ROWB + (kk + tg2) * 2;
                const char* p1 = sA + (r0 + 8) * ROWB + (kk + tg2) * 2;
                a[mi][0] = *(const uint32_t*)p0;
                a[mi][1] = *(const uint32_t*)p1;
                a[mi][2] = *(const uint32_t*)(p0 + 16);
                a[mi][3] = *(const uint32_t*)(p1 + 16);
            }
#pragma unroll
            for (int ni = 0; ni < 4; ni++) {
                int n0 = wc * 32 + ni * 8 + g;
                const char* p = sB + n0 * ROWB + (kk + tg2) * 2;
                b[ni][0] = *(const uint32_t*)p;
                b[ni][1] = *(const uint32_t*)(p + 16);
            }
#pragma unroll
            for (int mi = 0; mi < 4; mi++)
#pragma unroll
                for (int ni = 0; ni < 4; ni++)
                    mma_f16(acc[mi][ni], a[mi], b[ni]);
        }
        __syncthreads();
    }

    // epilogue: acc + bias -> out
#pragma unroll
    for (int mi = 0; mi < 4; mi++) {
        int grow0 = bx * BM + wr * 64 + mi * 16 + g;
#pragma unroll
        for (int ni = 0; ni < 4; ni++) {
            int gcol = by * BN + wc * 32 + ni * 8 + tg2;
            float b0 = bias[gcol], b1 = bias[gcol + 1];
            float2 v0 = {acc[mi][ni][0] + b0, acc[mi][ni][1] + b1};
            float2 v1 = {acc[mi][ni][2] + b0, acc[mi][ni][3] + b1};
            *(float2*)(out + (size_t)grow0 * NDIM + gcol) = v0;
            *(float2*)(out + (size_t)(grow0 + 8) * NDIM + gcol) = v1;
        }
    }
}

extern "C" void kernel_launch(void* const* d_in, const int* in_sizes, int n_in,
                              void* d_out, int out_size) {
    const float* x      = (const float*)d_in[0];  // [8192, 256, 8]
    const float* weight = (const float*)d_in[1];  // [256, 256, 8]
    const float* bias   = (const float*)d_in[2];  // [256, 8]
    const float* cayley = (const float*)d_in[3];  // [8, 8, 8]
    float* out = (float*)d_out;
    (void)in_sizes; (void)n_in; (void)out_size;

    cudaFuncSetAttribute(clifford_hmma_kernel,
                         cudaFuncAttributeMaxDynamicSharedMemorySize, SMEM_TOTAL);

    build_weff_kernel<<<(NDIM * KDIM) / 256, 256>>>(weight, cayley);

    dim3 grid(BATCH / BM, NDIM / BN);   // (64, 16)
    clifford_hmma_kernel<<<grid, 256, SMEM_TOTAL>>>(x, bias, out);
}